// round 8
// baseline (speedup 1.0000x reference)
#include <cuda_runtime.h>
#include <math.h>
#include <stdint.h>

#define BATCH 8
#define NSEQ  12306
#define NOUT  192                 // TS^3 * 3
#define PAIRS (BATCH * NOUT)      // 1536
#define CSIZE 8                   // cluster size = blocks per batch
#define MLP_BLOCKS (BATCH * CSIZE)   // 64
#define MLP_THR    1024

// TMA broadcast geometry: region = 2 pairs = 98448 B (16B multiple),
// 7 chunks of 14064 B (= 879 float4). Value boundary at byte 49224 =
// chunk 3, float4 #439 (bytes 7024..7040 -> a,a,b,b).
#define REGB    98448
#define CHUNK   14064
#define NCHUNK  7
#define CH4     (CHUNK / 16)      // 879
#define BC_BLOCKS (PAIRS / 2)     // 768
#define BC_THR  256

// Final MLP outputs (read by bcast kernel; kernel boundary orders memory)
__device__ float g_o[PAIRS];

// ---------- helpers ----------
__device__ __forceinline__ uint32_t smem_u32(const void* p)
{
    uint32_t a;
    asm("{ .reg .u64 t; cvta.to.shared.u64 t, %1; cvt.u32.u64 %0, t; }"
        : "=r"(a) : "l"(p));
    return a;
}

// Store {a,b} to smem word of CTA `rank` in this cluster.
__device__ __forceinline__ void dsmem_st64(uint32_t laddr, uint32_t rank,
                                           float a, float b)
{
    uint64_t v;
    asm("mov.b64 %0, {%1, %2};" : "=l"(v) : "f"(a), "f"(b));
    asm volatile("{ .reg .b32 r; mapa.shared::cluster.u32 r, %0, %1; "
                 "st.shared::cluster.b64 [r], %2; }"
                 :: "r"(laddr), "r"(rank), "l"(v) : "memory");
}

__device__ __forceinline__ void csync()
{
    asm volatile("barrier.cluster.arrive.aligned;" ::: "memory");
    asm volatile("barrier.cluster.wait.aligned;"   ::: "memory");
}

__device__ __forceinline__ float gelu_exact(float v)
{
    return 0.5f * v * (1.0f + erff(v * 0.70710678118654752440f));
}

// NPW neuron dot products of length K against smem row `in`; warp-collective.
template <int K, int NPW>
__device__ __forceinline__ void warp_dotN(const float* __restrict__ in,
                                          const float* __restrict__ W,
                                          int n0, int lane, float* acc)
{
    const float4* in4 = reinterpret_cast<const float4*>(in);
    const float4* wr[NPW];
#pragma unroll
    for (int j = 0; j < NPW; j++) {
        acc[j] = 0.0f;
        wr[j]  = reinterpret_cast<const float4*>(W + (size_t)(n0 + j) * K);
    }
#pragma unroll
    for (int i = lane; i < K / 4; i += 32) {
        float4 x4 = in4[i];
#pragma unroll
        for (int j = 0; j < NPW; j++) {
            float4 w4 = wr[j][i];
            acc[j] += w4.x * x4.x + w4.y * x4.y + w4.z * x4.z + w4.w * x4.w;
        }
    }
#pragma unroll
    for (int off = 16; off; off >>= 1)
#pragma unroll
        for (int j = 0; j < NPW; j++)
            acc[j] += __shfl_xor_sync(0xffffffffu, acc[j], off);
}

// ---------------- Kernel 1: MLP (unchanged from R7) ----------------
__global__ void __launch_bounds__(MLP_THR, 1) __cluster_dims__(CSIZE, 1, 1)
mlp_kernel(const float* __restrict__ x,
           const float* __restrict__ W1, const float* __restrict__ b1,
           const float* __restrict__ W2, const float* __restrict__ b2,
           const float* __restrict__ W3, const float* __restrict__ b3,
           const float* __restrict__ W4, const float* __restrict__ b4)
{
    __shared__ float A[1024];
    __shared__ float B[1024];

    const int bid   = blockIdx.x;
    const int g     = bid / CSIZE;
    const uint32_t rank = bid % CSIZE;
    const int wid   = threadIdx.x >> 5;
    const int lane  = threadIdx.x & 31;

    {
        const int t = bid * MLP_THR + threadIdx.x;
        const float* pf = nullptr;
        if      (t < 4096)  pf = W1 + (size_t)t * 32;
        else if (t < 20480) pf = W2 + (size_t)(t - 4096)  * 32;
        else if (t < 36864) pf = W3 + (size_t)(t - 20480) * 32;
        else if (t < 39936) pf = W4 + (size_t)(t - 36864) * 32;
        if (pf) asm volatile("prefetch.global.L2 [%0];" :: "l"(pf));
    }

    const uint32_t Aaddr = smem_u32(A);
    const uint32_t Baddr = smem_u32(B);

    if (threadIdx.x < 64)
        reinterpret_cast<float4*>(A)[threadIdx.x] =
            reinterpret_cast<const float4*>(x + (size_t)g * 256)[threadIdx.x];
    __syncthreads();

    // L1: A(256) -> 512
    {
        const int n = (int)rank * 64 + wid * 2;
        float acc[2];
        warp_dotN<256, 2>(A, W1, n, lane, acc);
        if (lane == 0) {
            float v0 = gelu_exact(acc[0] + b1[n]);
            float v1 = gelu_exact(acc[1] + b1[n + 1]);
#pragma unroll
            for (uint32_t r = 0; r < CSIZE; r++)
                dsmem_st64(Baddr + n * 4u, r, v0, v1);
        }
    }
    csync();

    // L2: B(512) -> 1024
    {
        const int n = (int)rank * 128 + wid * 4;
        float acc[4];
        warp_dotN<512, 4>(B, W2, n, lane, acc);
        if (lane == 0) {
            float v0 = gelu_exact(acc[0] + b2[n]);
            float v1 = gelu_exact(acc[1] + b2[n + 1]);
            float v2 = gelu_exact(acc[2] + b2[n + 2]);
            float v3 = gelu_exact(acc[3] + b2[n + 3]);
#pragma unroll
            for (uint32_t r = 0; r < CSIZE; r++) {
                dsmem_st64(Aaddr + n * 4u,     r, v0, v1);
                dsmem_st64(Aaddr + n * 4u + 8, r, v2, v3);
            }
        }
    }
    csync();

    // L3: A(1024) -> 512
    {
        const int n = (int)rank * 64 + wid * 2;
        float acc[2];
        warp_dotN<1024, 2>(A, W3, n, lane, acc);
        if (lane == 0) {
            float v0 = gelu_exact(acc[0] + b3[n]);
            float v1 = gelu_exact(acc[1] + b3[n + 1]);
#pragma unroll
            for (uint32_t r = 0; r < CSIZE; r++)
                dsmem_st64(Baddr + n * 4u, r, v0, v1);
        }
    }
    csync();

    // L4: B(512) -> 24 outputs/block, sigmoid
    if (wid < 24) {
        const int o = (int)rank * 24 + wid;
        float acc[1];
        warp_dotN<512, 1>(B, W4, o, lane, acc);
        if (lane == 0)
            g_o[g * NOUT + o] = 1.0f / (1.0f + expf(-(acc[0] + b4[o])));
    }
}

// ---------------- Kernel 2: broadcast via TMA bulk stores ----------------
// Each block owns 2 consecutive pairs: region of REGB bytes, streamed as
// NCHUNK SMEM chunks double-buffered through cp.async.bulk S2G.
__global__ void __launch_bounds__(BC_THR, 8)
bcast_tma_kernel(float* __restrict__ out)
{
    __shared__ __align__(16) float4 buf[2][CH4];

    const int reg = blockIdx.x;
    const float a = g_o[2 * reg];
    const float b = g_o[2 * reg + 1];
    const float4 va = make_float4(a, a, a, a);
    const float4 vb = make_float4(b, b, b, b);
    const float4 vm = make_float4(a, a, b, b);   // boundary float4

    char* dstBase = reinterpret_cast<char*>(out) + (size_t)reg * REGB;
    const int t = threadIdx.x;

#pragma unroll
    for (int c = 0; c < NCHUNK; c++) {
        // Buffer (c&1) was consumed by the bulk group issued at chunk c-2.
        if (c >= 2 && t == 0)
            asm volatile("cp.async.bulk.wait_group 1;" ::: "memory");
        __syncthreads();

        float4* Bf = buf[c & 1];
        if (c < 3) {
            for (int i = t; i < CH4; i += BC_THR) Bf[i] = va;
        } else if (c > 3) {
            for (int i = t; i < CH4; i += BC_THR) Bf[i] = vb;
        } else {
            for (int i = t; i < CH4; i += BC_THR)
                Bf[i] = (i < 439) ? va : (i > 439 ? vb : vm);
        }
        __syncthreads();

        if (t == 0) {
            asm volatile("fence.proxy.async.shared::cta;" ::: "memory");
            uint32_t saddr = smem_u32(Bf);
            asm volatile(
                "cp.async.bulk.global.shared::cta.bulk_group [%0], [%1], %2;"
                :: "l"(dstBase + (size_t)c * CHUNK), "r"(saddr), "r"((uint32_t)CHUNK)
                : "memory");
            asm volatile("cp.async.bulk.commit_group;" ::: "memory");
        }
    }

    if (t == 0)
        asm volatile("cp.async.bulk.wait_group 0;" ::: "memory");
}

extern "C" void kernel_launch(void* const* d_in, const int* in_sizes, int n_in,
                              void* d_out, int out_size)
{
    const float* x  = (const float*)d_in[0];
    const float* W1 = (const float*)d_in[1];
    const float* b1 = (const float*)d_in[2];
    const float* W2 = (const float*)d_in[3];
    const float* b2 = (const float*)d_in[4];
    const float* W3 = (const float*)d_in[5];
    const float* b3 = (const float*)d_in[6];
    const float* W4 = (const float*)d_in[7];
    const float* b4 = (const float*)d_in[8];

    mlp_kernel<<<MLP_BLOCKS, MLP_THR>>>(x, W1, b1, W2, b2, W3, b3, W4, b4);
    bcast_tma_kernel<<<BC_BLOCKS, BC_THR>>>((float*)d_out);
}

// round 9
// speedup vs baseline: 1.1441x; 1.1441x over previous
#include <cuda_runtime.h>
#include <math.h>
#include <stdint.h>

#define BATCH 8
#define NSEQ  12306
#define NOUT  192                 // TS^3 * 3
#define PAIRS (BATCH * NOUT)      // 1536
#define CSIZE 8                   // cluster size = blocks per batch
#define MLP_BLOCKS (BATCH * CSIZE)   // 64
#define MLP_THR    1024

#define BC_BLOCKS 592             // 148 SMs * 4 blocks (exactly one wave)
#define BC_THR    512
#define NQ4 4725504               // 1536*12306/4 float4 in output

// Final MLP outputs (read by bcast kernel; kernel boundary orders memory)
__device__ float g_o[PAIRS];

// ---------- helpers ----------
__device__ __forceinline__ uint32_t smem_u32(const void* p)
{
    uint32_t a;
    asm("{ .reg .u64 t; cvta.to.shared.u64 t, %1; cvt.u32.u64 %0, t; }"
        : "=r"(a) : "l"(p));
    return a;
}

__device__ __forceinline__ uint64_t policy_evict_last()
{
    uint64_t pol;
    asm("createpolicy.fractional.L2::evict_last.b64 %0, 1.0;" : "=l"(pol));
    return pol;
}

// Weight load: L2-sticky (evict_last) read-only vector load.
__device__ __forceinline__ float4 ldw(const float4* p, uint64_t pol)
{
    float4 v;
    asm volatile("ld.global.nc.L2::cache_hint.v4.f32 {%0,%1,%2,%3}, [%4], %5;"
                 : "=f"(v.x), "=f"(v.y), "=f"(v.z), "=f"(v.w)
                 : "l"(p), "l"(pol));
    return v;
}

// Streaming store (evict-first): don't let the 75.6MB output sweep L2.
__device__ __forceinline__ void stcs(float4* p, float4 v)
{
    asm volatile("st.global.cs.v4.f32 [%0], {%1,%2,%3,%4};"
                 :: "l"(p), "f"(v.x), "f"(v.y), "f"(v.z), "f"(v.w) : "memory");
}

// Store {a,b} to smem word of CTA `rank` in this cluster.
__device__ __forceinline__ void dsmem_st64(uint32_t laddr, uint32_t rank,
                                           float a, float b)
{
    uint64_t v;
    asm("mov.b64 %0, {%1, %2};" : "=l"(v) : "f"(a), "f"(b));
    asm volatile("{ .reg .b32 r; mapa.shared::cluster.u32 r, %0, %1; "
                 "st.shared::cluster.b64 [r], %2; }"
                 :: "r"(laddr), "r"(rank), "l"(v) : "memory");
}

__device__ __forceinline__ void csync()
{
    asm volatile("barrier.cluster.arrive.aligned;" ::: "memory");
    asm volatile("barrier.cluster.wait.aligned;"   ::: "memory");
}

__device__ __forceinline__ float gelu_exact(float v)
{
    return 0.5f * v * (1.0f + erff(v * 0.70710678118654752440f));
}

// NPW neuron dot products of length K against smem row `in`; warp-collective.
// Weights loaded with L2 evict_last policy.
template <int K, int NPW>
__device__ __forceinline__ void warp_dotN(const float* __restrict__ in,
                                          const float* __restrict__ W,
                                          int n0, int lane, uint64_t pol,
                                          float* acc)
{
    const float4* in4 = reinterpret_cast<const float4*>(in);
    const float4* wr[NPW];
#pragma unroll
    for (int j = 0; j < NPW; j++) {
        acc[j] = 0.0f;
        wr[j]  = reinterpret_cast<const float4*>(W + (size_t)(n0 + j) * K);
    }
#pragma unroll
    for (int i = lane; i < K / 4; i += 32) {
        float4 x4 = in4[i];
#pragma unroll
        for (int j = 0; j < NPW; j++) {
            float4 w4 = ldw(wr[j] + i, pol);
            acc[j] += w4.x * x4.x + w4.y * x4.y + w4.z * x4.z + w4.w * x4.w;
        }
    }
#pragma unroll
    for (int off = 16; off; off >>= 1)
#pragma unroll
        for (int j = 0; j < NPW; j++)
            acc[j] += __shfl_xor_sync(0xffffffffu, acc[j], off);
}

// ---------------- Kernel 1: MLP (one 8-CTA cluster per batch) ----------------
__global__ void __launch_bounds__(MLP_THR, 1) __cluster_dims__(CSIZE, 1, 1)
mlp_kernel(const float* __restrict__ x,
           const float* __restrict__ W1, const float* __restrict__ b1,
           const float* __restrict__ W2, const float* __restrict__ b2,
           const float* __restrict__ W3, const float* __restrict__ b3,
           const float* __restrict__ W4, const float* __restrict__ b4)
{
    __shared__ float A[1024];
    __shared__ float B[1024];

    const int bid   = blockIdx.x;
    const int g     = bid / CSIZE;          // batch 0..7
    const uint32_t rank = bid % CSIZE;      // cluster ctarank (1D launch)
    const int wid   = threadIdx.x >> 5;
    const int lane  = threadIdx.x & 31;

    const uint64_t pol = policy_evict_last();

    const uint32_t Aaddr = smem_u32(A);
    const uint32_t Baddr = smem_u32(B);

    // Stage x[g] (256 floats) locally into A.
    if (threadIdx.x < 64)
        reinterpret_cast<float4*>(A)[threadIdx.x] =
            reinterpret_cast<const float4*>(x + (size_t)g * 256)[threadIdx.x];
    __syncthreads();

    // ---- L1: A(256) -> 512, GELU. 2 neurons/warp -> B (replicated) ----
    {
        const int n = (int)rank * 64 + wid * 2;
        float acc[2];
        warp_dotN<256, 2>(A, W1, n, lane, pol, acc);
        if (lane == 0) {
            float v0 = gelu_exact(acc[0] + b1[n]);
            float v1 = gelu_exact(acc[1] + b1[n + 1]);
#pragma unroll
            for (uint32_t r = 0; r < CSIZE; r++)
                dsmem_st64(Baddr + n * 4u, r, v0, v1);
        }
    }
    csync();

    // ---- L2: B(512) -> 1024, GELU. 4 neurons/warp -> A (replicated) ----
    {
        const int n = (int)rank * 128 + wid * 4;
        float acc[4];
        warp_dotN<512, 4>(B, W2, n, lane, pol, acc);
        if (lane == 0) {
            float v0 = gelu_exact(acc[0] + b2[n]);
            float v1 = gelu_exact(acc[1] + b2[n + 1]);
            float v2 = gelu_exact(acc[2] + b2[n + 2]);
            float v3 = gelu_exact(acc[3] + b2[n + 3]);
#pragma unroll
            for (uint32_t r = 0; r < CSIZE; r++) {
                dsmem_st64(Aaddr + n * 4u,     r, v0, v1);
                dsmem_st64(Aaddr + n * 4u + 8, r, v2, v3);
            }
        }
    }
    csync();

    // ---- L3: A(1024) -> 512, GELU. 2 neurons/warp -> B (replicated) ----
    {
        const int n = (int)rank * 64 + wid * 2;
        float acc[2];
        warp_dotN<1024, 2>(A, W3, n, lane, pol, acc);
        if (lane == 0) {
            float v0 = gelu_exact(acc[0] + b3[n]);
            float v1 = gelu_exact(acc[1] + b3[n + 1]);
#pragma unroll
            for (uint32_t r = 0; r < CSIZE; r++)
                dsmem_st64(Baddr + n * 4u, r, v0, v1);
        }
    }
    csync();

    // ---- L4: B(512) -> 24 outputs/block, sigmoid -> g_o ----
    if (wid < 24) {
        const int o = (int)rank * 24 + wid;     // 0..191
        float acc[1];
        warp_dotN<512, 1>(B, W4, o, lane, pol, acc);
        if (lane == 0)
            g_o[g * NOUT + o] = 1.0f / (1.0f + expf(-(acc[0] + b4[o])));
    }
}

// ---------------- Kernel 2: broadcast (one wave, streaming stores) ----------
// out.flat[j] = g_o[j / NSEQ]. NSEQ % 4 == 2: a float4 straddles a pair
// boundary iff r == NSEQ-2.
__global__ void __launch_bounds__(BC_THR, 4)
bcast_kernel(float* __restrict__ out)
{
    float4* o4 = reinterpret_cast<float4*>(out);
    const unsigned stride = BC_BLOCKS * BC_THR;

    for (unsigned q = blockIdx.x * BC_THR + threadIdx.x; q < NQ4; q += stride) {
        const unsigned j = q << 2;
        const unsigned p = j / NSEQ;            // const-divide -> mulhi chain
        const unsigned r = j - p * NSEQ;
        const float a = __ldg(&g_o[p]);
        float4 v;
        if (r == NSEQ - 2) {                    // rare straddle (a,a,b,b)
            const float b = __ldg(&g_o[p + 1]);
            v = make_float4(a, a, b, b);
        } else {
            v = make_float4(a, a, a, a);
        }
        stcs(o4 + q, v);
    }
}

extern "C" void kernel_launch(void* const* d_in, const int* in_sizes, int n_in,
                              void* d_out, int out_size)
{
    const float* x  = (const float*)d_in[0];
    const float* W1 = (const float*)d_in[1];
    const float* b1 = (const float*)d_in[2];
    const float* W2 = (const float*)d_in[3];
    const float* b2 = (const float*)d_in[4];
    const float* W3 = (const float*)d_in[5];
    const float* b3 = (const float*)d_in[6];
    const float* W4 = (const float*)d_in[7];
    const float* b4 = (const float*)d_in[8];

    mlp_kernel<<<MLP_BLOCKS, MLP_THR>>>(x, W1, b1, W2, b2, W3, b3, W4, b4);
    bcast_kernel<<<BC_BLOCKS, BC_THR>>>((float*)d_out);
}